// round 1
// baseline (speedup 1.0000x reference)
#include <cuda_runtime.h>
#include <cstddef>

// Problem constants
#define Bb 8
#define Ss 1024
#define Hh 256
#define LL 7
#define BSR (Bb*Ss)        // 8192 rows
#define H7 (7*Hh)          // 1792
#define H3 (3*Hh)          // 768
#define NCH 16             // chunks for S-dim reductions
#define SCH (Ss/NCH)       // 64

// ---------------- scratch (device globals; no allocations allowed) ----------
__device__ float d_hbuf0[BSR*Hh];
__device__ float d_hbuf1[BSR*Hh];
__device__ float d_cbuf0[BSR*Hh];
__device__ float d_cbuf1[BSR*Hh];
__device__ float d_proj[(size_t)BSR*H7];
__device__ float d_zbuf[(size_t)BSR*H7];
__device__ float d_ctx[(size_t)BSR*H3];
__device__ float d_ph[BSR*Hh];
__device__ float d_W3[H3*H7];
__device__ float d_pi[Bb*H3];
__device__ float d_pa[Bb*2*Hh];
__device__ float d_igb[Bb*Hh];
__device__ float d_ogb[Bb*Hh];
__device__ float d_gh[Bb*Hh];
__device__ float d_gcv[Bb*Hh];
__device__ float d_havg[Bb*Hh];
__device__ float d_gWg[Bb*H7];
__device__ float d_pnum[Bb*NCH*Hh];
__device__ float d_pden[Bb*NCH*Hh];
__device__ float d_invms[Bb];

// ---------------- helpers ----------------------------------------------------
__device__ __forceinline__ float2 blockSum2(float a, float b, float* sh) {
    #pragma unroll
    for (int o = 16; o > 0; o >>= 1) {
        a += __shfl_down_sync(0xffffffffu, a, o);
        b += __shfl_down_sync(0xffffffffu, b, o);
    }
    int w = threadIdx.x >> 5, l = threadIdx.x & 31;
    if (l == 0) { sh[w] = a; sh[8 + w] = b; }
    __syncthreads();
    if (threadIdx.x == 0) {
        float sa = 0.f, sb = 0.f;
        #pragma unroll
        for (int i = 0; i < 8; i++) { sa += sh[i]; sb += sh[8 + i]; }
        sh[16] = sa; sh[17] = sb;
    }
    __syncthreads();
    float2 r = make_float2(sh[16], sh[17]);
    __syncthreads();   // protect sh before next reuse
    return r;
}

__device__ __forceinline__ float sigmoidf_(float x) { return 1.f / (1.f + expf(-x)); }

// ---------------- tiled SGEMM: C[M,N] = A[M,K] @ W[K,N] (+bias) --------------
// Requires M%128==0, N%128==0, K%16==0 (true for all uses here).
#define GBM 128
#define GBN 128
#define GBK 16
#define GTM 8
#define GTN 8

__global__ __launch_bounds__(256) void k_sgemm(
    int M, int N, int K,
    const float* __restrict__ A, const float* __restrict__ W,
    const float* __restrict__ bias, float* __restrict__ C)
{
    __shared__ float As[GBK][GBM];
    __shared__ float Bs[GBK][GBN];
    int tid = threadIdx.x;
    int brow = blockIdx.y, bcol = blockIdx.x;
    const float* Ab = A + (size_t)brow * GBM * K;
    const float* Wb = W + (size_t)bcol * GBN;
    float acc[GTM][GTN];
    #pragma unroll
    for (int m = 0; m < GTM; m++)
        #pragma unroll
        for (int n = 0; n < GTN; n++) acc[m][n] = 0.f;

    int tr = tid / (GBN / GTN);          // 0..15
    int tc = tid % (GBN / GTN);          // 0..15
    int arow = tid / (GBK / 4);          // 0..63
    int acol = (tid % (GBK / 4)) * 4;    // 0,4,8,12
    int brw  = tid / (GBN / 4);          // 0..7
    int bcl  = (tid % (GBN / 4)) * 4;    // 0..124

    for (int k0 = 0; k0 < K; k0 += GBK) {
        #pragma unroll
        for (int i = 0; i < 2; i++) {
            int r = arow + i * 64;
            float4 v = *(const float4*)(Ab + (size_t)r * K + k0 + acol);
            As[acol + 0][r] = v.x; As[acol + 1][r] = v.y;
            As[acol + 2][r] = v.z; As[acol + 3][r] = v.w;
        }
        #pragma unroll
        for (int i = 0; i < 2; i++) {
            int r = brw + i * 8;
            float4 v = *(const float4*)(Wb + (size_t)(k0 + r) * N + bcl);
            *(float4*)&Bs[r][bcl] = v;
        }
        __syncthreads();
        #pragma unroll
        for (int k = 0; k < GBK; k++) {
            float ra[GTM], rb[GTN];
            #pragma unroll
            for (int m = 0; m < GTM; m++) ra[m] = As[k][tr * GTM + m];
            #pragma unroll
            for (int n = 0; n < GTN; n++) rb[n] = Bs[k][tc * GTN + n];
            #pragma unroll
            for (int m = 0; m < GTM; m++)
                #pragma unroll
                for (int n = 0; n < GTN; n++)
                    acc[m][n] += ra[m] * rb[n];
        }
        __syncthreads();
    }
    int cbase = bcol * GBN + tc * GTN;
    #pragma unroll
    for (int m = 0; m < GTM; m++) {
        size_t r = (size_t)brow * GBM + tr * GTM + m;
        #pragma unroll
        for (int n = 0; n < GTN; n += 4) {
            float4 v;
            v.x = acc[m][n];     v.y = acc[m][n + 1];
            v.z = acc[m][n + 2]; v.w = acc[m][n + 3];
            if (bias) {
                v.x += bias[cbase + n];     v.y += bias[cbase + n + 1];
                v.z += bias[cbase + n + 2]; v.w += bias[cbase + n + 3];
            }
            *(float4*)(C + r * N + cbase + n) = v;
        }
    }
}

// ---------------- tiny GEMM for M=8 rows -------------------------------------
__global__ void k_smallgemm(int M, int N, int K,
                            const float* __restrict__ A, const float* __restrict__ W,
                            const float* __restrict__ bias, float* __restrict__ C)
{
    int idx = blockIdx.x * blockDim.x + threadIdx.x;
    if (idx >= M * N) return;
    int m = idx / N, n = idx % N;
    float acc = bias ? bias[n] : 0.f;
    const float* a = A + (size_t)m * K;
    for (int k = 0; k < K; k++) acc += a[k] * W[(size_t)k * N + n];
    C[idx] = acc;
}

// ---------------- small kernels ----------------------------------------------
__global__ void k_invms(const float* __restrict__ mask, float* __restrict__ invms)
{
    __shared__ float sh[8];
    int b = blockIdx.x, t = threadIdx.x;
    float a = 0.f;
    for (int s = t; s < Ss; s += 256) a += mask[b * Ss + s];
    #pragma unroll
    for (int o = 16; o > 0; o >>= 1) a += __shfl_down_sync(0xffffffffu, a, o);
    if ((t & 31) == 0) sh[t >> 5] = a;
    __syncthreads();
    if (t == 0) {
        float s2 = 0.f;
        #pragma unroll
        for (int i = 0; i < 8; i++) s2 += sh[i];
        invms[b] = 1.f / s2;
    }
}

__global__ void k_meanp(const float* __restrict__ x, const float* __restrict__ mask,
                        float* __restrict__ pnum)
{
    int ch = blockIdx.x, b = blockIdx.y, h = threadIdx.x;
    float acc = 0.f;
    int s0 = ch * SCH;
    #pragma unroll 8
    for (int i = 0; i < SCH; i++) {
        int s = s0 + i;
        acc += x[((size_t)(b * Ss + s)) * Hh + h] * mask[b * Ss + s];
    }
    pnum[(b * NCH + ch) * Hh + h] = acc;
}

__global__ void k_meanf(const float* __restrict__ pnum, const float* __restrict__ invms,
                        float* __restrict__ out)
{
    int b = blockIdx.x, h = threadIdx.x;
    float a = 0.f;
    #pragma unroll
    for (int c = 0; c < NCH; c++) a += pnum[(b * NCH + c) * Hh + h];
    out[b * Hh + h] = a * invms[b];
}

__global__ void k_igog(const float* __restrict__ pi, const float* __restrict__ pa,
                       const float* __restrict__ lns, const float* __restrict__ lnb,
                       float* __restrict__ ig, float* __restrict__ og)
{
    __shared__ float sh[18];
    int b = blockIdx.x, h = threadIdx.x;
    // ig: ln0( pi[:, :H] + pa[:, :H] )
    float v = pi[b * H3 + h] + pa[b * 2 * Hh + h];
    float2 ssum = blockSum2(v, v * v, sh);
    float m = ssum.x * (1.f / 256.f);
    float var = (ssum.y - 256.f * m * m) * (1.f / 255.f);
    float zn = lns[0 * Hh + h] * (v - m) * rsqrtf(var + 1e-6f) + lnb[0 * Hh + h];
    ig[b * Hh + h] = sigmoidf_(zn);
    // og: ln2( pi[:, 2H:] + pa[:, H:] )
    v = pi[b * H3 + 2 * Hh + h] + pa[b * 2 * Hh + Hh + h];
    ssum = blockSum2(v, v * v, sh);
    m = ssum.x * (1.f / 256.f);
    var = (ssum.y - 256.f * m * m) * (1.f / 255.f);
    zn = lns[2 * Hh + h] * (v - m) * rsqrtf(var + 1e-6f) + lnb[2 * Hh + h];
    og[b * Hh + h] = sigmoidf_(zn);
}

__global__ void k_hg(const float* __restrict__ ph, const float* __restrict__ pi,
                     const float* __restrict__ mask,
                     const float* __restrict__ lns, const float* __restrict__ lnb,
                     float* __restrict__ hg)
{
    __shared__ float sh[18];
    int bs = blockIdx.x; int b = bs >> 10;
    int h = threadIdx.x;
    float v = ph[(size_t)bs * Hh + h] + pi[b * H3 + Hh + h];
    float2 ssum = blockSum2(v, v * v, sh);
    float m = ssum.x * (1.f / 256.f);
    float var = (ssum.y - 256.f * m * m) * (1.f / 255.f);
    float zn = lns[1 * Hh + h] * (v - m) * rsqrtf(var + 1e-6f) + lnb[1 * Hh + h];
    float sg = sigmoidf_(zn);
    hg[(size_t)bs * Hh + h] = sg + (mask[bs] * 1e25f - 1e25f);
}

__global__ void k_gcp(const float* __restrict__ hg, const float* __restrict__ cell,
                      float* __restrict__ pnum, float* __restrict__ pden)
{
    int ch = blockIdx.x, b = blockIdx.y, h = threadIdx.x;
    float num = 0.f, den = 0.f;
    int s0 = ch * SCH;
    #pragma unroll 4
    for (int i = 0; i < SCH; i++) {
        size_t idx = ((size_t)(b * Ss + s0 + i)) * Hh + h;
        float e = expf(hg[idx]);              // bounded above by e; -1e25 -> 0
        num += e * cell[idx];
        den += e;
    }
    pnum[(b * NCH + ch) * Hh + h] = num;
    pden[(b * NCH + ch) * Hh + h] = den;
}

__global__ void k_gcf(const float* __restrict__ pnum, const float* __restrict__ pden,
                      const float* __restrict__ ig, const float* __restrict__ og,
                      float* __restrict__ gc, float* __restrict__ gh)
{
    int b = blockIdx.x, h = threadIdx.x;
    float num = 0.f, den = 0.f;
    #pragma unroll
    for (int c = 0; c < NCH; c++) {
        num += pnum[(b * NCH + c) * Hh + h];
        den += pden[(b * NCH + c) * Hh + h];
    }
    float ei = expf(ig[b * Hh + h]);
    float g = (gc[b * Hh + h] * ei + num) / (ei + den);
    gc[b * Hh + h] = g;
    gh[b * Hh + h] = og[b * Hh + h] * tanhf(g);
}

__global__ void k_ctx(const float* __restrict__ hid, float* __restrict__ ctx)
{
    int i = blockIdx.x * blockDim.x + threadIdx.x;   // float4 index
    if (i >= BSR * (H3 / 4)) return;
    int bs = i / (H3 / 4);
    int j = (i % (H3 / 4)) * 4;
    int s = bs & (Ss - 1);
    float4 v = make_float4(0.f, 0.f, 0.f, 0.f);
    if (j < Hh) {
        if (s > 0) v = *(const float4*)(hid + ((size_t)bs - 1) * Hh + j);
    } else if (j < 2 * Hh) {
        v = *(const float4*)(hid + (size_t)bs * Hh + (j - Hh));
    } else {
        if (s < Ss - 1) v = *(const float4*)(hid + ((size_t)bs + 1) * Hh + (j - 2 * Hh));
    }
    *(float4*)(ctx + (size_t)bs * H3 + j) = v;
}

__global__ void k_w3(const float* __restrict__ Wc, const float* __restrict__ Wh,
                     float* __restrict__ W3)
{
    int i = blockIdx.x * blockDim.x + threadIdx.x;
    if (i >= H3 * H7) return;
    int r = i / H7, c = i % H7;
    float v;
    if (r < Hh)            v = Wc[(size_t)r * H7 + c];          // h_l rows
    else if (r < 2 * Hh)   v = Wh[(size_t)(r - Hh) * H7 + c];   // h   rows
    else                   v = Wc[(size_t)(r - Hh) * H7 + c];   // h_r rows (Wc rows 256..511)
    W3[i] = v;
}

__global__ __launch_bounds__(256) void k_update(
    const float* __restrict__ z, const float* __restrict__ proj,
    const float* __restrict__ gWg, const float* __restrict__ gc,
    const float* __restrict__ mask,
    const float* __restrict__ lns, const float* __restrict__ lnb,
    const float* __restrict__ c_old,
    float* __restrict__ h_new, float* __restrict__ c_new)
{
    __shared__ float sh[18];
    int bs = blockIdx.x; int b = bs >> 10; int s = bs & (Ss - 1);
    int h = threadIdx.x;
    size_t rz = (size_t)bs * H7;
    float zn[7];
    #pragma unroll
    for (int k = 0; k < 7; k++) {
        float v = z[rz + k * Hh + h] + proj[rz + k * Hh + h] + gWg[b * H7 + k * Hh + h];
        float2 ssum = blockSum2(v, v * v, sh);
        float m = ssum.x * (1.f / 256.f);
        float var = (ssum.y - 256.f * m * m) * (1.f / 255.f);
        zn[k] = lns[(3 + k) * Hh + h] * (v - m) * rsqrtf(var + 1e-6f) + lnb[(3 + k) * Hh + h];
    }
    float e[6], den = 0.f;
    #pragma unroll
    for (int k = 0; k < 6; k++) {
        float sg = sigmoidf_(zn[k]);
        e[k] = expf(sg);       // sigmoid in (0,1): no max-sub needed
        den += e[k];
    }
    float inv = 1.f / den;
    float mem = tanhf(zn[6]);
    size_t idx = (size_t)bs * Hh + h;
    float c  = c_old[idx];
    float cl = (s > 0)      ? c_old[idx - Hh] : 0.f;
    float cr = (s < Ss - 1) ? c_old[idx + Hh] : 0.f;
    // gates order: i, l, r, f, gl, o
    float cn = (e[1] * cl + e[2] * cr + e[3] * c + e[0] * mem + e[4] * gc[b * Hh + h]) * inv;
    float mk = mask[bs];
    h_new[idx] = e[5] * inv * tanhf(cn) * mk;
    c_new[idx] = cn * mk;
}

// ---------------- orchestration ----------------------------------------------
extern "C" void kernel_launch(void* const* d_in, const int* in_sizes, int n_in,
                              void* d_out, int out_size)
{
    (void)in_sizes; (void)n_in; (void)out_size;
    const float* inputs = (const float*)d_in[0];
    const float* mask   = (const float*)d_in[1];
    const float* ih     = (const float*)d_in[2];
    const float* ic     = (const float*)d_in[3];
    const float* Wc     = (const float*)d_in[4];
    const float* Wh     = (const float*)d_in[5];
    const float* Wi     = (const float*)d_in[6];
    const float* bi     = (const float*)d_in[7];
    const float* Wg     = (const float*)d_in[8];
    const float* Gi     = (const float*)d_in[9];
    const float* gb     = (const float*)d_in[10];
    const float* Gh     = (const float*)d_in[11];
    const float* Ga     = (const float*)d_in[12];
    const float* lns    = (const float*)d_in[13];
    const float* lnb    = (const float*)d_in[14];
    float* out = (float*)d_out;

    float *hb0, *hb1, *cb0, *cb1, *proj, *zb, *ctx, *ph, *W3;
    float *pi, *pa, *ig, *og, *gh, *gc, *havg, *gWg, *pnum, *pden, *invms;
    cudaGetSymbolAddress((void**)&hb0,  d_hbuf0);
    cudaGetSymbolAddress((void**)&hb1,  d_hbuf1);
    cudaGetSymbolAddress((void**)&cb0,  d_cbuf0);
    cudaGetSymbolAddress((void**)&cb1,  d_cbuf1);
    cudaGetSymbolAddress((void**)&proj, d_proj);
    cudaGetSymbolAddress((void**)&zb,   d_zbuf);
    cudaGetSymbolAddress((void**)&ctx,  d_ctx);
    cudaGetSymbolAddress((void**)&ph,   d_ph);
    cudaGetSymbolAddress((void**)&W3,   d_W3);
    cudaGetSymbolAddress((void**)&pi,   d_pi);
    cudaGetSymbolAddress((void**)&pa,   d_pa);
    cudaGetSymbolAddress((void**)&ig,   d_igb);
    cudaGetSymbolAddress((void**)&og,   d_ogb);
    cudaGetSymbolAddress((void**)&gh,   d_gh);
    cudaGetSymbolAddress((void**)&gc,   d_gcv);
    cudaGetSymbolAddress((void**)&havg, d_havg);
    cudaGetSymbolAddress((void**)&gWg,  d_gWg);
    cudaGetSymbolAddress((void**)&pnum, d_pnum);
    cudaGetSymbolAddress((void**)&pden, d_pden);
    cudaGetSymbolAddress((void**)&invms, d_invms);

    // layer-invariant precompute
    k_invms<<<Bb, 256>>>(mask, invms);
    k_meanp<<<dim3(NCH, Bb), 256>>>(ih, mask, pnum);
    k_meanf<<<Bb, 256>>>(pnum, invms, gh);                       // g_h init
    k_meanp<<<dim3(NCH, Bb), 256>>>(ic, mask, pnum);
    k_meanf<<<Bb, 256>>>(pnum, invms, gc);                       // g_c init
    k_w3<<<(H3 * H7 + 255) / 256, 256>>>(Wc, Wh, W3);
    k_sgemm<<<dim3(H7 / GBN, BSR / GBM), 256>>>(BSR, H7, Hh, inputs, Wi, bi, proj);

    float* hbufs[2] = { hb0, hb1 };
    float* cbufs[2] = { cb0, cb1 };

    for (int l = 0; l < LL; l++) {
        const float* hid = (l == 0) ? ih : hbufs[l & 1];
        const float* cel = (l == 0) ? ic : cbufs[l & 1];
        float* hout = (l == LL - 1) ? out : hbufs[(l + 1) & 1];
        float* cout = cbufs[(l + 1) & 1];

        // ---- global state ----
        k_meanp<<<dim3(NCH, Bb), 256>>>(hid, mask, pnum);
        k_meanf<<<Bb, 256>>>(pnum, invms, havg);
        k_smallgemm<<<(Bb * H3 + 255) / 256, 256>>>(Bb, H3, Hh, gh, Gi, gb, pi);
        k_smallgemm<<<(Bb * 2 * Hh + 255) / 256, 256>>>(Bb, 2 * Hh, Hh, havg, Ga, (const float*)nullptr, pa);
        k_sgemm<<<dim3(Hh / GBN, BSR / GBM), 256>>>(BSR, Hh, Hh, hid, Gh, (const float*)nullptr, ph);
        k_igog<<<Bb, 256>>>(pi, pa, lns, lnb, ig, og);
        k_hg<<<BSR, 256>>>(ph, pi, mask, lns, lnb, ph);          // in-place: ph -> hg
        k_gcp<<<dim3(NCH, Bb), 256>>>(ph, cel, pnum, pden);
        k_gcf<<<Bb, 256>>>(pnum, pden, ig, og, gc, gh);
        k_smallgemm<<<(Bb * H7 + 255) / 256, 256>>>(Bb, H7, Hh, gh, Wg, (const float*)nullptr, gWg);

        // ---- per-word state ----
        k_ctx<<<(BSR * (H3 / 4) + 255) / 256, 256>>>(hid, ctx);
        k_sgemm<<<dim3(H7 / GBN, BSR / GBM), 256>>>(BSR, H7, H3, ctx, W3, (const float*)nullptr, zb);
        k_update<<<BSR, 256>>>(zb, proj, gWg, gc, mask, lns, lnb, cel, hout, cout);
    }
}

// round 3
// speedup vs baseline: 1.6926x; 1.6926x over previous
#include <cuda_runtime.h>
#include <cuda_bf16.h>
#include <cstdint>
#include <cstddef>

// Problem constants
#define Bb 8
#define Ss 1024
#define Hh 256
#define LL 7
#define BSR (Bb*Ss)        // 8192 rows
#define H7 (7*Hh)          // 1792
#define H3 (3*Hh)          // 768
#define NCH 16
#define SCH (Ss/NCH)

// ---------------- scratch (device globals; no allocations allowed) ----------
__device__ float d_hbuf0[BSR*Hh];
__device__ float d_hbuf1[BSR*Hh];
__device__ float d_cbuf0[BSR*Hh];
__device__ float d_cbuf1[BSR*Hh];
__device__ float d_proj[(size_t)BSR*H7];
__device__ float d_zbuf[(size_t)BSR*H7];
__device__ float d_ph[BSR*Hh];
__device__ float d_pi[Bb*H3];
__device__ float d_pa[Bb*2*Hh];
__device__ float d_igb[Bb*Hh];
__device__ float d_ogb[Bb*Hh];
__device__ float d_gh[Bb*Hh];
__device__ float d_gcv[Bb*Hh];
__device__ float d_havg[Bb*Hh];
__device__ float d_gWg[Bb*H7];
__device__ float d_pnum[Bb*NCH*Hh];
__device__ float d_pden[Bb*NCH*Hh];
__device__ float d_invms[Bb];
// split-bf16 activations / weights (16B aligned for uint4 / cp.async)
__device__ __align__(16) __nv_bfloat16 d_ctx_hi[(size_t)BSR*H3];
__device__ __align__(16) __nv_bfloat16 d_ctx_lo[(size_t)BSR*H3];
__device__ __align__(16) __nv_bfloat16 d_h_hi0[BSR*Hh];
__device__ __align__(16) __nv_bfloat16 d_h_lo0[BSR*Hh];
__device__ __align__(16) __nv_bfloat16 d_h_hi1[BSR*Hh];
__device__ __align__(16) __nv_bfloat16 d_h_lo1[BSR*Hh];
__device__ __align__(16) __nv_bfloat16 d_in_hi[BSR*Hh];
__device__ __align__(16) __nv_bfloat16 d_in_lo[BSR*Hh];
__device__ __align__(16) __nv_bfloat16 d_W3T_hi[H7*H3];
__device__ __align__(16) __nv_bfloat16 d_W3T_lo[H7*H3];
__device__ __align__(16) __nv_bfloat16 d_GhT_hi[Hh*Hh];
__device__ __align__(16) __nv_bfloat16 d_GhT_lo[Hh*Hh];
__device__ __align__(16) __nv_bfloat16 d_WiT_hi[H7*Hh];
__device__ __align__(16) __nv_bfloat16 d_WiT_lo[H7*Hh];

// ---------------- PTX helpers -----------------------------------------------
__device__ __forceinline__ uint32_t smem_u32(const void* p) {
    uint32_t a;
    asm("{ .reg .u64 t; cvta.to.shared.u64 t, %1; cvt.u32.u64 %0, t; }"
        : "=r"(a) : "l"(p));
    return a;
}
__device__ __forceinline__ void cpasync16(uint32_t dst, const void* src) {
    asm volatile("cp.async.cg.shared.global [%0], [%1], 16;" :: "r"(dst), "l"(src));
}
#define CP_COMMIT() asm volatile("cp.async.commit_group;" ::: "memory")
#define CP_WAIT1()  asm volatile("cp.async.wait_group 1;" ::: "memory")
#define CP_WAIT0()  asm volatile("cp.async.wait_group 0;" ::: "memory")

__device__ __forceinline__ void mma16816(float* c, const uint32_t* a, const uint32_t* b) {
    asm volatile(
        "mma.sync.aligned.m16n8k16.row.col.f32.bf16.bf16.f32 "
        "{%0,%1,%2,%3}, {%4,%5,%6,%7}, {%8,%9}, {%0,%1,%2,%3};"
        : "+f"(c[0]), "+f"(c[1]), "+f"(c[2]), "+f"(c[3])
        : "r"(a[0]), "r"(a[1]), "r"(a[2]), "r"(a[3]), "r"(b[0]), "r"(b[1]));
}

// ---------------- bf16x3 HMMA GEMM -------------------------------------------
// C[M,N] = (Ahi+Alo)[M,K] @ (Bhi+Blo)^T  with B stored [N,K] K-major.
// M%128==0, N%128==0, K%32==0.
#define KB 32
#define SA 40                      // padded smem row stride (halves) -> bank-conflict-free
#define MTILE (128*SA)             // halves per matrix tile
#define STAGE (4*MTILE)            // Ahi, Alo, Bhi, Blo
#define HSMEM (2*STAGE*2)          // bytes: 2 stages

__global__ void __launch_bounds__(256, 1) k_hmma(
    int M, int N, int K,
    const __nv_bfloat16* __restrict__ Ahi, const __nv_bfloat16* __restrict__ Alo,
    const __nv_bfloat16* __restrict__ Bhi, const __nv_bfloat16* __restrict__ Blo,
    const float* __restrict__ bias, float* __restrict__ C)
{
    extern __shared__ __nv_bfloat16 sm[];
    int tid = threadIdx.x, wid = tid >> 5, lane = tid & 31;
    int gID = lane >> 2, tg = lane & 3;
    int warp_m = wid >> 2, warp_n = wid & 3;
    int arow0 = blockIdx.y * 128, bcol0 = blockIdx.x * 128;

    const __nv_bfloat16* srcs[4] = {
        Ahi + (size_t)arow0 * K, Alo + (size_t)arow0 * K,
        Bhi + (size_t)bcol0 * K, Blo + (size_t)bcol0 * K };

    float acc[4][4][4];
    #pragma unroll
    for (int mi = 0; mi < 4; mi++)
        #pragma unroll
        for (int ni = 0; ni < 4; ni++)
            #pragma unroll
            for (int q = 0; q < 4; q++) acc[mi][ni][q] = 0.f;

    uint32_t smbase = smem_u32(sm);
    int niter = K / KB;

    // prologue: stage 0
    {
        #pragma unroll
        for (int t = 0; t < 4; t++) {
            const __nv_bfloat16* src = srcs[t];
            uint32_t dst = smbase + (0 * STAGE + t * MTILE) * 2;
            #pragma unroll
            for (int s = 0; s < 2; s++) {
                int slot = tid + s * 256;
                int row = slot >> 2, cg = (slot & 3) * 8;
                cpasync16(dst + (row * SA + cg) * 2, src + (size_t)row * K + cg);
            }
        }
        CP_COMMIT();
    }

    for (int it = 0; it < niter; it++) {
        if (it + 1 < niter) {
            int st = (it + 1) & 1;
            int k0 = (it + 1) * KB;
            #pragma unroll
            for (int t = 0; t < 4; t++) {
                const __nv_bfloat16* src = srcs[t] + k0;
                uint32_t dst = smbase + (st * STAGE + t * MTILE) * 2;
                #pragma unroll
                for (int s = 0; s < 2; s++) {
                    int slot = tid + s * 256;
                    int row = slot >> 2, cg = (slot & 3) * 8;
                    cpasync16(dst + (row * SA + cg) * 2, src + (size_t)row * K + cg);
                }
            }
            CP_COMMIT();
            CP_WAIT1();
        } else {
            CP_WAIT0();
        }
        __syncthreads();

        const __nv_bfloat16* As_h = sm + (it & 1) * STAGE;
        const __nv_bfloat16* As_l = As_h + MTILE;
        const __nv_bfloat16* Bs_h = As_h + 2 * MTILE;
        const __nv_bfloat16* Bs_l = As_h + 3 * MTILE;

        #pragma unroll
        for (int kk = 0; kk < KB; kk += 16) {
            uint32_t bh[4][2], bl[4][2];
            #pragma unroll
            for (int ni = 0; ni < 4; ni++) {
                int n = warp_n * 32 + ni * 8 + gID;
                const __nv_bfloat16* ph_ = Bs_h + n * SA + kk + tg * 2;
                const __nv_bfloat16* pl_ = Bs_l + n * SA + kk + tg * 2;
                bh[ni][0] = *(const uint32_t*)ph_;
                bh[ni][1] = *(const uint32_t*)(ph_ + 8);
                bl[ni][0] = *(const uint32_t*)pl_;
                bl[ni][1] = *(const uint32_t*)(pl_ + 8);
            }
            #pragma unroll
            for (int mi = 0; mi < 4; mi++) {
                int r0 = warp_m * 64 + mi * 16 + gID;
                const __nv_bfloat16* ah_ = As_h + r0 * SA + kk + tg * 2;
                const __nv_bfloat16* al_ = As_l + r0 * SA + kk + tg * 2;
                uint32_t ah[4], al[4];
                ah[0] = *(const uint32_t*)ah_;
                ah[1] = *(const uint32_t*)(ah_ + 8 * SA);
                ah[2] = *(const uint32_t*)(ah_ + 8);
                ah[3] = *(const uint32_t*)(ah_ + 8 * SA + 8);
                al[0] = *(const uint32_t*)al_;
                al[1] = *(const uint32_t*)(al_ + 8 * SA);
                al[2] = *(const uint32_t*)(al_ + 8);
                al[3] = *(const uint32_t*)(al_ + 8 * SA + 8);
                #pragma unroll
                for (int ni = 0; ni < 4; ni++) {
                    mma16816(acc[mi][ni], ah, bh[ni]);
                    mma16816(acc[mi][ni], ah, bl[ni]);
                    mma16816(acc[mi][ni], al, bh[ni]);
                }
            }
        }
        __syncthreads();
    }

    // epilogue
    #pragma unroll
    for (int mi = 0; mi < 4; mi++) {
        #pragma unroll
        for (int ni = 0; ni < 4; ni++) {
            int r = arow0 + warp_m * 64 + mi * 16 + gID;
            int c = bcol0 + warp_n * 32 + ni * 8 + tg * 2;
            float b0 = bias ? bias[c] : 0.f;
            float b1 = bias ? bias[c + 1] : 0.f;
            float2 v0 = make_float2(acc[mi][ni][0] + b0, acc[mi][ni][1] + b1);
            float2 v1 = make_float2(acc[mi][ni][2] + b0, acc[mi][ni][3] + b1);
            *(float2*)(C + (size_t)r * N + c) = v0;
            *(float2*)(C + (size_t)(r + 8) * N + c) = v1;
        }
    }
}

// ---------------- helpers ----------------------------------------------------
__device__ __forceinline__ float2 blockSum2(float a, float b, float* sh) {
    #pragma unroll
    for (int o = 16; o > 0; o >>= 1) {
        a += __shfl_down_sync(0xffffffffu, a, o);
        b += __shfl_down_sync(0xffffffffu, b, o);
    }
    int w = threadIdx.x >> 5, l = threadIdx.x & 31;
    if (l == 0) { sh[w] = a; sh[8 + w] = b; }
    __syncthreads();
    if (threadIdx.x == 0) {
        float sa = 0.f, sb2 = 0.f;
        #pragma unroll
        for (int i = 0; i < 8; i++) { sa += sh[i]; sb2 += sh[8 + i]; }
        sh[16] = sa; sh[17] = sb2;
    }
    __syncthreads();
    float2 r = make_float2(sh[16], sh[17]);
    __syncthreads();
    return r;
}
__device__ __forceinline__ float sigmoidf_(float x) { return 1.f / (1.f + expf(-x)); }
__device__ __forceinline__ void splitbf(float v, __nv_bfloat16& hi, __nv_bfloat16& lo) {
    hi = __float2bfloat16(v);
    lo = __float2bfloat16(v - __bfloat162float(hi));
}

// ---------------- split / transpose kernels ----------------------------------
__global__ void k_split(const float* __restrict__ x, __nv_bfloat16* __restrict__ hi,
                        __nv_bfloat16* __restrict__ lo, int n)
{
    int i = blockIdx.x * blockDim.x + threadIdx.x;
    if (i >= n) return;
    splitbf(x[i], hi[i], lo[i]);
}

__global__ void k_w3t(const float* __restrict__ Wc, const float* __restrict__ Wh,
                      __nv_bfloat16* __restrict__ hi, __nv_bfloat16* __restrict__ lo)
{
    int i = blockIdx.x * blockDim.x + threadIdx.x;   // [H7 x H3] (N-major, K inner)
    if (i >= H7 * H3) return;
    int n = i / H3, k = i % H3;
    float v = (k < Hh) ? Wc[(size_t)k * H7 + n]
            : (k < 2 * Hh) ? Wh[(size_t)(k - Hh) * H7 + n]
            : Wc[(size_t)(k - Hh) * H7 + n];
    splitbf(v, hi[i], lo[i]);
}

__global__ void k_wt(const float* __restrict__ W, int K, int N,
                     __nv_bfloat16* __restrict__ hi, __nv_bfloat16* __restrict__ lo)
{
    int i = blockIdx.x * blockDim.x + threadIdx.x;   // [N x K]
    if (i >= N * K) return;
    int n = i / K, k = i % K;
    splitbf(W[(size_t)k * N + n], hi[i], lo[i]);
}

// ---------------- tiny GEMM for M=8 rows -------------------------------------
__global__ void k_smallgemm(int M, int N, int K,
                            const float* __restrict__ A, const float* __restrict__ W,
                            const float* __restrict__ bias, float* __restrict__ C)
{
    int idx = blockIdx.x * blockDim.x + threadIdx.x;
    if (idx >= M * N) return;
    int m = idx / N, n = idx % N;
    float acc = bias ? bias[n] : 0.f;
    const float* a = A + (size_t)m * K;
    for (int k = 0; k < K; k++) acc += a[k] * W[(size_t)k * N + n];
    C[idx] = acc;
}

// ---------------- small kernels ----------------------------------------------
__global__ void k_invms(const float* __restrict__ mask, float* __restrict__ invms)
{
    __shared__ float sh[8];
    int b = blockIdx.x, t = threadIdx.x;
    float a = 0.f;
    for (int s = t; s < Ss; s += 256) a += mask[b * Ss + s];
    #pragma unroll
    for (int o = 16; o > 0; o >>= 1) a += __shfl_down_sync(0xffffffffu, a, o);
    if ((t & 31) == 0) sh[t >> 5] = a;
    __syncthreads();
    if (t == 0) {
        float s2 = 0.f;
        #pragma unroll
        for (int i = 0; i < 8; i++) s2 += sh[i];
        invms[b] = 1.f / s2;
    }
}

__global__ void k_meanp(const float* __restrict__ x, const float* __restrict__ mask,
                        float* __restrict__ pnum)
{
    int ch = blockIdx.x, b = blockIdx.y, h = threadIdx.x;
    float acc = 0.f;
    int s0 = ch * SCH;
    #pragma unroll 8
    for (int i = 0; i < SCH; i++) {
        int s = s0 + i;
        acc += x[((size_t)(b * Ss + s)) * Hh + h] * mask[b * Ss + s];
    }
    pnum[(b * NCH + ch) * Hh + h] = acc;
}

__global__ void k_meanf(const float* __restrict__ pnum, const float* __restrict__ invms,
                        float* __restrict__ out)
{
    int b = blockIdx.x, h = threadIdx.x;
    float a = 0.f;
    #pragma unroll
    for (int c = 0; c < NCH; c++) a += pnum[(b * NCH + c) * Hh + h];
    out[b * Hh + h] = a * invms[b];
}

__global__ void k_igog(const float* __restrict__ pi, const float* __restrict__ pa,
                       const float* __restrict__ lns, const float* __restrict__ lnb,
                       float* __restrict__ ig, float* __restrict__ og)
{
    __shared__ float sh[18];
    int b = blockIdx.x, h = threadIdx.x;
    float v = pi[b * H3 + h] + pa[b * 2 * Hh + h];
    float2 ssum = blockSum2(v, v * v, sh);
    float m = ssum.x * (1.f / 256.f);
    float var = (ssum.y - 256.f * m * m) * (1.f / 255.f);
    float zn = lns[h] * (v - m) * rsqrtf(var + 1e-6f) + lnb[h];
    ig[b * Hh + h] = sigmoidf_(zn);
    v = pi[b * H3 + 2 * Hh + h] + pa[b * 2 * Hh + Hh + h];
    ssum = blockSum2(v, v * v, sh);
    m = ssum.x * (1.f / 256.f);
    var = (ssum.y - 256.f * m * m) * (1.f / 255.f);
    zn = lns[2 * Hh + h] * (v - m) * rsqrtf(var + 1e-6f) + lnb[2 * Hh + h];
    og[b * Hh + h] = sigmoidf_(zn);
}

__global__ void k_hg(const float* __restrict__ ph, const float* __restrict__ pi,
                     const float* __restrict__ mask,
                     const float* __restrict__ lns, const float* __restrict__ lnb,
                     float* __restrict__ hg)
{
    __shared__ float sh[18];
    int bs = blockIdx.x; int b = bs >> 10;
    int h = threadIdx.x;
    float v = ph[(size_t)bs * Hh + h] + pi[b * H3 + Hh + h];
    float2 ssum = blockSum2(v, v * v, sh);
    float m = ssum.x * (1.f / 256.f);
    float var = (ssum.y - 256.f * m * m) * (1.f / 255.f);
    float zn = lns[Hh + h] * (v - m) * rsqrtf(var + 1e-6f) + lnb[Hh + h];
    hg[(size_t)bs * Hh + h] = sigmoidf_(zn) + (mask[bs] * 1e25f - 1e25f);
}

__global__ void k_gcp(const float* __restrict__ hg, const float* __restrict__ cell,
                      float* __restrict__ pnum, float* __restrict__ pden)
{
    int ch = blockIdx.x, b = blockIdx.y, h = threadIdx.x;
    float num = 0.f, den = 0.f;
    int s0 = ch * SCH;
    #pragma unroll 4
    for (int i = 0; i < SCH; i++) {
        size_t idx = ((size_t)(b * Ss + s0 + i)) * Hh + h;
        float e = expf(hg[idx]);
        num += e * cell[idx];
        den += e;
    }
    pnum[(b * NCH + ch) * Hh + h] = num;
    pden[(b * NCH + ch) * Hh + h] = den;
}

__global__ void k_gcf(const float* __restrict__ pnum, const float* __restrict__ pden,
                      const float* __restrict__ ig, const float* __restrict__ og,
                      float* __restrict__ gc, float* __restrict__ gh)
{
    int b = blockIdx.x, h = threadIdx.x;
    float num = 0.f, den = 0.f;
    #pragma unroll
    for (int c = 0; c < NCH; c++) {
        num += pnum[(b * NCH + c) * Hh + h];
        den += pden[(b * NCH + c) * Hh + h];
    }
    float ei = expf(ig[b * Hh + h]);
    float g = (gc[b * Hh + h] * ei + num) / (ei + den);
    gc[b * Hh + h] = g;
    gh[b * Hh + h] = og[b * Hh + h] * tanhf(g);
}

// build split-bf16 ctx = [h_l, h, h_r] directly from split-bf16 hidden
__global__ void k_ctx_bf(const __nv_bfloat16* __restrict__ hhi,
                         const __nv_bfloat16* __restrict__ hlo,
                         __nv_bfloat16* __restrict__ chi,
                         __nv_bfloat16* __restrict__ clo)
{
    int i = blockIdx.x * blockDim.x + threadIdx.x;  // 8-elem chunk
    if (i >= BSR * (H3 / 8)) return;
    int bs = i / (H3 / 8);
    int j = (i % (H3 / 8)) * 8;
    int s = bs & (Ss - 1);
    uint4 vh = make_uint4(0, 0, 0, 0), vl = make_uint4(0, 0, 0, 0);
    long off = -1;
    if (j < Hh)           { if (s > 0)      off = ((long)bs - 1) * Hh + j; }
    else if (j < 2 * Hh)  {                 off = (long)bs * Hh + (j - Hh); }
    else                  { if (s < Ss - 1) off = ((long)bs + 1) * Hh + (j - 2 * Hh); }
    if (off >= 0) {
        vh = *(const uint4*)(hhi + off);
        vl = *(const uint4*)(hlo + off);
    }
    *(uint4*)(chi + (size_t)bs * H3 + j) = vh;
    *(uint4*)(clo + (size_t)bs * H3 + j) = vl;
}

__global__ __launch_bounds__(256) void k_update(
    const float* __restrict__ z, const float* __restrict__ proj,
    const float* __restrict__ gWg, const float* __restrict__ gc,
    const float* __restrict__ mask,
    const float* __restrict__ lns, const float* __restrict__ lnb,
    const float* __restrict__ c_old,
    float* __restrict__ h_new, float* __restrict__ c_new,
    __nv_bfloat16* __restrict__ hhi, __nv_bfloat16* __restrict__ hlo)
{
    __shared__ float sh[18];
    int bs = blockIdx.x; int b = bs >> 10; int s = bs & (Ss - 1);
    int h = threadIdx.x;
    size_t rz = (size_t)bs * H7;
    float zn[7];
    #pragma unroll
    for (int k = 0; k < 7; k++) {
        float v = z[rz + k * Hh + h] + proj[rz + k * Hh + h] + gWg[b * H7 + k * Hh + h];
        float2 ssum = blockSum2(v, v * v, sh);
        float m = ssum.x * (1.f / 256.f);
        float var = (ssum.y - 256.f * m * m) * (1.f / 255.f);
        zn[k] = lns[(3 + k) * Hh + h] * (v - m) * rsqrtf(var + 1e-6f) + lnb[(3 + k) * Hh + h];
    }
    float e[6], den = 0.f;
    #pragma unroll
    for (int k = 0; k < 6; k++) {
        e[k] = expf(sigmoidf_(zn[k]));
        den += e[k];
    }
    float inv = 1.f / den;
    float mem = tanhf(zn[6]);
    size_t idx = (size_t)bs * Hh + h;
    float c  = c_old[idx];
    float cl = (s > 0)      ? c_old[idx - Hh] : 0.f;
    float cr = (s < Ss - 1) ? c_old[idx + Hh] : 0.f;
    float cn = (e[1] * cl + e[2] * cr + e[3] * c + e[0] * mem + e[4] * gc[b * Hh + h]) * inv;
    float mk = mask[bs];
    float hv = e[5] * inv * tanhf(cn) * mk;
    h_new[idx] = hv;
    c_new[idx] = cn * mk;
    splitbf(hv, hhi[idx], hlo[idx]);
}

// ---------------- orchestration ----------------------------------------------
extern "C" void kernel_launch(void* const* d_in, const int* in_sizes, int n_in,
                              void* d_out, int out_size)
{
    (void)in_sizes; (void)n_in; (void)out_size;
    const float* inputs = (const float*)d_in[0];
    const float* mask   = (const float*)d_in[1];
    const float* ih     = (const float*)d_in[2];
    const float* ic     = (const float*)d_in[3];
    const float* Wc     = (const float*)d_in[4];
    const float* Wh     = (const float*)d_in[5];
    const float* Wi     = (const float*)d_in[6];
    const float* bi     = (const float*)d_in[7];
    const float* Wg     = (const float*)d_in[8];
    const float* Gi     = (const float*)d_in[9];
    const float* gb     = (const float*)d_in[10];
    const float* Gh     = (const float*)d_in[11];
    const float* Ga     = (const float*)d_in[12];
    const float* lns    = (const float*)d_in[13];
    const float* lnb    = (const float*)d_in[14];
    float* out = (float*)d_out;

    float *hb0, *hb1, *cb0, *cb1, *proj, *zb, *ph;
    float *pi, *pa, *ig, *og, *gh, *gc, *havg, *gWg, *pnum, *pden, *invms;
    __nv_bfloat16 *chi, *clo, *hh0, *hl0, *hh1, *hl1, *inh, *inl;
    __nv_bfloat16 *w3h, *w3l, *ghh, *ghl, *wih, *wil;
    cudaGetSymbolAddress((void**)&hb0,  d_hbuf0);
    cudaGetSymbolAddress((void**)&hb1,  d_hbuf1);
    cudaGetSymbolAddress((void**)&cb0,  d_cbuf0);
    cudaGetSymbolAddress((void**)&cb1,  d_cbuf1);
    cudaGetSymbolAddress((void**)&proj, d_proj);
    cudaGetSymbolAddress((void**)&zb,   d_zbuf);
    cudaGetSymbolAddress((void**)&ph,   d_ph);
    cudaGetSymbolAddress((void**)&pi,   d_pi);
    cudaGetSymbolAddress((void**)&pa,   d_pa);
    cudaGetSymbolAddress((void**)&ig,   d_igb);
    cudaGetSymbolAddress((void**)&og,   d_ogb);
    cudaGetSymbolAddress((void**)&gh,   d_gh);
    cudaGetSymbolAddress((void**)&gc,   d_gcv);
    cudaGetSymbolAddress((void**)&havg, d_havg);
    cudaGetSymbolAddress((void**)&gWg,  d_gWg);
    cudaGetSymbolAddress((void**)&pnum, d_pnum);
    cudaGetSymbolAddress((void**)&pden, d_pden);
    cudaGetSymbolAddress((void**)&invms, d_invms);
    cudaGetSymbolAddress((void**)&chi, d_ctx_hi);
    cudaGetSymbolAddress((void**)&clo, d_ctx_lo);
    cudaGetSymbolAddress((void**)&hh0, d_h_hi0);
    cudaGetSymbolAddress((void**)&hl0, d_h_lo0);
    cudaGetSymbolAddress((void**)&hh1, d_h_hi1);
    cudaGetSymbolAddress((void**)&hl1, d_h_lo1);
    cudaGetSymbolAddress((void**)&inh, d_in_hi);
    cudaGetSymbolAddress((void**)&inl, d_in_lo);
    cudaGetSymbolAddress((void**)&w3h, d_W3T_hi);
    cudaGetSymbolAddress((void**)&w3l, d_W3T_lo);
    cudaGetSymbolAddress((void**)&ghh, d_GhT_hi);
    cudaGetSymbolAddress((void**)&ghl, d_GhT_lo);
    cudaGetSymbolAddress((void**)&wih, d_WiT_hi);
    cudaGetSymbolAddress((void**)&wil, d_WiT_lo);

    cudaFuncSetAttribute(k_hmma, cudaFuncAttributeMaxDynamicSharedMemorySize, HSMEM);

    // layer-invariant precompute
    k_invms<<<Bb, 256>>>(mask, invms);
    k_meanp<<<dim3(NCH, Bb), 256>>>(ih, mask, pnum);
    k_meanf<<<Bb, 256>>>(pnum, invms, gh);
    k_meanp<<<dim3(NCH, Bb), 256>>>(ic, mask, pnum);
    k_meanf<<<Bb, 256>>>(pnum, invms, gc);
    k_w3t<<<(H7 * H3 + 255) / 256, 256>>>(Wc, Wh, w3h, w3l);
    k_wt<<<(Hh * Hh + 255) / 256, 256>>>(Gh, Hh, Hh, ghh, ghl);
    k_wt<<<(H7 * Hh + 255) / 256, 256>>>(Wi, Hh, H7, wih, wil);
    k_split<<<(BSR * Hh + 255) / 256, 256>>>(ih, hh0, hl0, BSR * Hh);
    k_split<<<(BSR * Hh + 255) / 256, 256>>>(inputs, inh, inl, BSR * Hh);
    k_hmma<<<dim3(H7 / 128, BSR / 128), 256, HSMEM>>>(
        BSR, H7, Hh, inh, inl, wih, wil, bi, proj);

    float* hbufs[2] = { hb0, hb1 };
    float* cbufs[2] = { cb0, cb1 };
    __nv_bfloat16* hhis[2] = { hh0, hh1 };
    __nv_bfloat16* hlos[2] = { hl0, hl1 };

    for (int l = 0; l < LL; l++) {
        const float* hid = (l == 0) ? ih : hbufs[l & 1];
        const float* cel = (l == 0) ? ic : cbufs[l & 1];
        const __nv_bfloat16* hhi = hhis[l & 1];
        const __nv_bfloat16* hlo = hlos[l & 1];
        float* hout = (l == LL - 1) ? out : hbufs[(l + 1) & 1];
        float* cout = cbufs[(l + 1) & 1];

        // ---- global state ----
        k_meanp<<<dim3(NCH, Bb), 256>>>(hid, mask, pnum);
        k_meanf<<<Bb, 256>>>(pnum, invms, havg);
        k_smallgemm<<<(Bb * H3 + 255) / 256, 256>>>(Bb, H3, Hh, gh, Gi, gb, pi);
        k_smallgemm<<<(Bb * 2 * Hh + 255) / 256, 256>>>(Bb, 2 * Hh, Hh, havg, Ga,
                                                        (const float*)nullptr, pa);
        k_hmma<<<dim3(Hh / 128, BSR / 128), 256, HSMEM>>>(
            BSR, Hh, Hh, hhi, hlo, ghh, ghl, (const float*)nullptr, ph);
        k_igog<<<Bb, 256>>>(pi, pa, lns, lnb, ig, og);
        k_hg<<<BSR, 256>>>(ph, pi, mask, lns, lnb, ph);
        k_gcp<<<dim3(NCH, Bb), 256>>>(ph, cel, pnum, pden);
        k_gcf<<<Bb, 256>>>(pnum, pden, ig, og, gc, gh);
        k_smallgemm<<<(Bb * H7 + 255) / 256, 256>>>(Bb, H7, Hh, gh, Wg,
                                                    (const float*)nullptr, gWg);

        // ---- per-word state ----
        k_ctx_bf<<<(BSR * (H3 / 8) + 255) / 256, 256>>>(hhi, hlo, chi, clo);
        k_hmma<<<dim3(H7 / 128, BSR / 128), 256, HSMEM>>>(
            BSR, H7, H3, chi, clo, w3h, w3l, (const float*)nullptr, zb);
        k_update<<<BSR, 256>>>(zb, proj, gWg, gc, mask, lns, lnb, cel, hout, cout,
                               hhis[(l + 1) & 1], hlos[(l + 1) & 1]);
    }
}